// round 4
// baseline (speedup 1.0000x reference)
#include <cuda_runtime.h>

#define TPB  192
#define MAXB 8192
#define EB   224     // event-term blocks

__device__ float        g_part[MAXB];
__device__ unsigned int g_ctr = 0;

__device__ __forceinline__ float rcp_approx(float x) {
    float r; asm("rcp.approx.f32 %0, %1;" : "=f"(r) : "f"(x)); return r;
}
__device__ __forceinline__ float ex2_approx(float x) {
    float r; asm("ex2.approx.f32 %0, %1;" : "=f"(r) : "f"(x)); return r;
}
#define L2E 1.4426950408889634f

// A&S 7.1.26 full-range erf (abs err < 1.5e-7), 2 MUFU (rcp + ex2)
__device__ __forceinline__ float erf_as(float x) {
    float s  = copysignf(1.0f, x);
    float ax = fabsf(x);
    float t  = rcp_approx(fmaf(0.3275911f, ax, 1.0f));
    float P  = t * fmaf(t, fmaf(t, fmaf(t, fmaf(t, 1.061405429f, -1.453152027f),
                                        1.421413741f), -0.284496736f), 0.254829592f);
    float e  = ex2_approx(-ax * ax * L2E);
    return s * fmaf(-P, e, 1.0f);
}

// Exact Taylor erf for |x| <= 0.71 (abs err < 3e-5, 0 MUFU); takes u = x*x
__device__ __forceinline__ float erf_small(float x, float u) {
    float p = fmaf(u, fmaf(u, fmaf(u, fmaf(u, 4.6296296e-3f, -2.3809524e-2f),
                                   0.1f), -0.33333334f), 1.0f);
    return 1.1283791671f * x * p;
}

__device__ __forceinline__ float block_reduce_sum(float v) {
    __shared__ float s[32];
    int lane = threadIdx.x & 31;
    int w    = threadIdx.x >> 5;
    #pragma unroll
    for (int o = 16; o; o >>= 1) v += __shfl_xor_sync(0xffffffffu, v, o);
    if (lane == 0) s[w] = v;
    __syncthreads();
    v = (threadIdx.x < (TPB >> 5)) ? s[threadIdx.x] : 0.0f;
    if (w == 0) {
        #pragma unroll
        for (int o = 16; o; o >>= 1) v += __shfl_xor_sync(0xffffffffu, v, o);
    }
    return v;  // valid in thread 0
}

// One pair term. T0ZERO: t0 == 0 (warp-uniform), enables fused fast path.
template <bool T0ZERO>
__device__ __forceinline__ float pair_term(float2 zi, float2 vi,
                                           float2 zj, float2 vj,
                                           float b, float t0, float tn) {
    float dzx = zi.x - zj.x, dzy = zi.y - zj.y;
    float dvx = vi.x - vj.x, dvy = vi.y - vj.y;

    float a2 = fmaf(dzx, dzx, dzy * dzy);
    float b2 = fmaf(dvx, dvx, dvy * dvy);
    float ab = fmaf(dzx, dvx, dzy * dvy);

    float rb = rsqrtf(b2);            // 1/bnorm
    float bn = b2 * rb;               // bnorm
    float q  = ab * rb;               // bn*mu = ab/bn, |q| <= 1/sqrt(2)
    float u  = q * q;
    float earg  = (b - a2) + u;       // b - a2 + ab*mu
    float pref0 = 0.88622692545275801f * rb;
    float pref  = ex2_approx(earg * L2E) * pref0;

    if (T0ZERO) {
        float e0 = erf_small(q, u);
        float x1 = fmaf(bn, tn, q);
        float s  = copysignf(1.0f, x1);
        float ax = fabsf(x1);
        float t  = rcp_approx(fmaf(0.3275911f, ax, 1.0f));
        float P  = t * fmaf(t, fmaf(t, fmaf(t, fmaf(t, 1.061405429f, -1.453152027f),
                                            1.421413741f), -0.284496736f), 0.254829592f);
        // pref*e1 = pref*s - pref0 * exp(earg - x1^2) * s*P   (exp fused)
        float S  = ex2_approx(fmaf(-x1, x1, earg) * L2E);
        return fmaf(pref, s - e0, -pref0 * S * (s * P));
    } else {
        float e1 = erf_as(fmaf(bn, tn, q));
        float e0 = erf_as(fmaf(bn, t0, q));
        return pref * (e1 - e0);
    }
}

// Process group g = rows (2g, 2g+1) against all j > i. Branch-free inner loop.
template <bool T0ZERO>
__device__ __forceinline__ float group_pairs(const float2* __restrict__ z0,
                                             const float2* __restrict__ v0,
                                             int g, int n,
                                             float b, float t0, float tn) {
    int i0 = 2 * g;
    if (i0 >= n - 1) return 0.0f;
    int i1 = i0 + 1;

    const float2 zi0 = __ldg(&z0[i0]);
    const float2 vi0 = __ldg(&v0[i0]);
    float acc = 0.0f;

    if (i1 >= n) {
        // degenerate single row (n odd, last group)
        for (int j = i0 + 1 + (int)threadIdx.x; j < n; j += TPB)
            acc += pair_term<T0ZERO>(zi0, vi0, __ldg(&z0[j]), __ldg(&v0[j]),
                                     b, t0, tn);
        return acc;
    }

    const float2 zi1 = __ldg(&z0[i1]);
    const float2 vi1 = __ldg(&v0[i1]);

    // peel the (i0, i1) pair: exactly one thread does it
    if (threadIdx.x == 0)
        acc += pair_term<T0ZERO>(zi0, vi0, zi1, vi1, b, t0, tn);

    // branch-free: both rows valid for all j >= i0+2
    #pragma unroll 2
    for (int j = i0 + 2 + (int)threadIdx.x; j < n; j += TPB) {
        float2 zj = __ldg(&z0[j]);
        float2 vj = __ldg(&v0[j]);
        acc += pair_term<T0ZERO>(zi0, vi0, zj, vj, b, t0, tn);
        acc += pair_term<T0ZERO>(zi1, vi1, zj, vj, b, t0, tn);
    }
    return acc;
}

__global__ void __launch_bounds__(TPB)
cvm_fused(const int2*   __restrict__ idx,
          const float*  __restrict__ t,
          const float2* __restrict__ z0,
          const float2* __restrict__ v0,
          const float*  __restrict__ t0p,
          const float*  __restrict__ tnp,
          const float*  __restrict__ betap,
          float*        __restrict__ out,
          int n, int n_events, int pb, int eb) {
    const float b = __ldg(betap);
    float acc = 0.0f;

    if ((int)blockIdx.x < pb) {
        const float t0 = __ldg(t0p);
        const float tn = __ldg(tnp);
        const int nhalf = (n + 1) >> 1;       // # of 2-row groups
        const int units = nhalf >> 1;         // folded unit count
        const int g0 = blockIdx.x;
        const int g1 = nhalf - 1 - g0;        // folded partner (const work/unit)
        const bool t0z = (t0 == 0.0f);

        if (t0z) {
            if (g0 < units || g0 == g1) acc += group_pairs<true>(z0, v0, g0, n, b, t0, tn);
            if (g1 > g0)                acc += group_pairs<true>(z0, v0, g1, n, b, t0, tn);
        } else {
            if (g0 < units || g0 == g1) acc += group_pairs<false>(z0, v0, g0, n, b, t0, tn);
            if (g1 > g0)                acc += group_pairs<false>(z0, v0, g1, n, b, t0, tn);
        }
    } else {
        // ---- event blocks: sum ||dz + dv*t||^2 ----
        int start = ((int)blockIdx.x - pb) * TPB + threadIdx.x;
        int stride = eb * TPB;
        for (int e = start; e < n_events; e += stride) {
            int2  ij = __ldg(&idx[e]);
            float te = __ldg(&t[e]);
            float2 zi = __ldg(&z0[ij.x]);
            float2 zj = __ldg(&z0[ij.y]);
            float2 vi = __ldg(&v0[ij.x]);
            float2 vj = __ldg(&v0[ij.y]);
            float dx = fmaf(vi.x - vj.x, te, zi.x - zj.x);
            float dy = fmaf(vi.y - vj.y, te, zi.y - zj.y);
            acc = fmaf(dx, dx, acc);
            acc = fmaf(dy, dy, acc);
        }
    }

    float bs = block_reduce_sum(acc);
    __shared__ unsigned int s_rank;
    if (threadIdx.x == 0) {
        g_part[blockIdx.x] = bs;
        __threadfence();
        s_rank = atomicAdd(&g_ctr, 1u);
    }
    __syncthreads();

    // ---- last finished block: final reduction + output ----
    if (s_rank == gridDim.x - 1) {
        __threadfence();
        double d = 0.0;
        for (int i = threadIdx.x; i < (int)gridDim.x; i += TPB)
            d += (double)g_part[i];
        __shared__ double sd[32];
        int lane = threadIdx.x & 31, w = threadIdx.x >> 5;
        #pragma unroll
        for (int o = 16; o; o >>= 1) d += __shfl_xor_sync(0xffffffffu, d, o);
        if (lane == 0) sd[w] = d;
        __syncthreads();
        d = (threadIdx.x < (TPB >> 5)) ? sd[threadIdx.x] : 0.0;
        if (w == 0) {
            #pragma unroll
            for (int o = 16; o; o >>= 1) d += __shfl_xor_sync(0xffffffffu, d, o);
        }
        if (threadIdx.x == 0) {
            out[0] = (float)((double)n_events * (double)b - d);
            g_ctr = 0;             // self-reset for next graph replay
            __threadfence();
        }
    }
}

extern "C" void kernel_launch(void* const* d_in, const int* in_sizes, int n_in,
                              void* d_out, int out_size) {
    const int2*   idx  = (const int2*)d_in[0];    // (N_EVENTS, 2) int32
    const float*  t    = (const float*)d_in[1];   // (N_EVENTS,)
    const float*  t0   = (const float*)d_in[2];   // scalar
    const float*  tn   = (const float*)d_in[3];   // scalar
    const float2* z0   = (const float2*)d_in[4];  // (N_POINTS, 2)
    const float2* v0   = (const float2*)d_in[5];  // (N_POINTS, 2)
    const float*  beta = (const float*)d_in[6];   // (1,1)

    const int n_events = in_sizes[1];
    const int n_points = in_sizes[4] / 2;

    const int nhalf = (n_points + 1) / 2;   // 2-row groups
    int pb = (nhalf + 1) / 2;               // folded units (block per unit)
    if (pb < 1) pb = 1;
    int eb = EB;
    int grid = pb + eb;                     // 1250 + 224 = 1474 <= 1480 slots
    if (grid > MAXB) { grid = MAXB; eb = grid - pb; }

    cvm_fused<<<grid, TPB>>>(idx, t, z0, v0, t0, tn, beta,
                             (float*)d_out, n_points, n_events, pb, eb);
}

// round 5
// speedup vs baseline: 1.0659x; 1.0659x over previous
#include <cuda_runtime.h>

#define TPB  256
#define MAXB 8192

__device__ float        g_part[MAXB];
__device__ unsigned int g_ctr = 0;

__device__ __forceinline__ float rcp_approx(float x) {
    float r; asm("rcp.approx.f32 %0, %1;" : "=f"(r) : "f"(x)); return r;
}
__device__ __forceinline__ float ex2_approx(float x) {
    float r; asm("ex2.approx.f32 %0, %1;" : "=f"(r) : "f"(x)); return r;
}
#define L2E 1.4426950408889634f

// A&S 7.1.26 full-range erf (abs err < 1.5e-7), 2 MUFU (rcp + ex2)
__device__ __forceinline__ float erf_as(float x) {
    float s  = copysignf(1.0f, x);
    float ax = fabsf(x);
    float t  = rcp_approx(fmaf(0.3275911f, ax, 1.0f));
    float P  = t * fmaf(t, fmaf(t, fmaf(t, fmaf(t, 1.061405429f, -1.453152027f),
                                        1.421413741f), -0.284496736f), 0.254829592f);
    float e  = ex2_approx(-ax * ax * L2E);
    return s * fmaf(-P, e, 1.0f);
}

// Exact Taylor erf for |x| <= 0.71 (abs err < 3e-5, 0 MUFU); takes u = x*x
__device__ __forceinline__ float erf_small(float x, float u) {
    float p = fmaf(u, fmaf(u, fmaf(u, fmaf(u, 4.6296296e-3f, -2.3809524e-2f),
                                   0.1f), -0.33333334f), 1.0f);
    return 1.1283791671f * x * p;
}

__device__ __forceinline__ float block_reduce_sum(float v) {
    __shared__ float s[32];
    int lane = threadIdx.x & 31;
    int w    = threadIdx.x >> 5;
    #pragma unroll
    for (int o = 16; o; o >>= 1) v += __shfl_xor_sync(0xffffffffu, v, o);
    if (lane == 0) s[w] = v;
    __syncthreads();
    v = (threadIdx.x < (TPB >> 5)) ? s[threadIdx.x] : 0.0f;
    if (w == 0) {
        #pragma unroll
        for (int o = 16; o; o >>= 1) v += __shfl_xor_sync(0xffffffffu, v, o);
    }
    return v;  // valid in thread 0
}

// One pair term. T0ZERO: t0 == 0 (warp-uniform), enables fused fast path.
template <bool T0ZERO>
__device__ __forceinline__ float pair_term(float2 zi, float2 vi,
                                           float2 zj, float2 vj,
                                           float b, float t0, float tn) {
    float dzx = zi.x - zj.x, dzy = zi.y - zj.y;
    float dvx = vi.x - vj.x, dvy = vi.y - vj.y;

    float a2 = fmaf(dzx, dzx, dzy * dzy);
    float b2 = fmaf(dvx, dvx, dvy * dvy);
    float ab = fmaf(dzx, dvx, dzy * dvy);

    float rb = rsqrtf(b2);            // 1/bnorm
    float bn = b2 * rb;               // bnorm
    float q  = ab * rb;               // bn*mu = ab/bn, |q| <= 1/sqrt(2)
    float u  = q * q;
    float earg  = (b - a2) + u;       // b - a2 + ab*mu
    float pref0 = 0.88622692545275801f * rb;
    float pref  = ex2_approx(earg * L2E) * pref0;

    if (T0ZERO) {
        float e0 = erf_small(q, u);
        float x1 = fmaf(bn, tn, q);
        float s  = copysignf(1.0f, x1);
        float ax = fabsf(x1);
        float t  = rcp_approx(fmaf(0.3275911f, ax, 1.0f));
        float P  = t * fmaf(t, fmaf(t, fmaf(t, fmaf(t, 1.061405429f, -1.453152027f),
                                            1.421413741f), -0.284496736f), 0.254829592f);
        // pref*e1 = pref*s - pref0 * exp(earg - x1^2) * s*P   (exp fused)
        float S  = ex2_approx(fmaf(-x1, x1, earg) * L2E);
        return fmaf(pref, s - e0, -pref0 * S * (s * P));
    } else {
        float e1 = erf_as(fmaf(bn, tn, q));
        float e0 = erf_as(fmaf(bn, t0, q));
        return pref * (e1 - e0);
    }
}

// Process group g = rows (2g, 2g+1) against all j > i. Branch-free inner loop.
template <bool T0ZERO>
__device__ __forceinline__ float group_pairs(const float2* __restrict__ z0,
                                             const float2* __restrict__ v0,
                                             int g, int n,
                                             float b, float t0, float tn) {
    int i0 = 2 * g;
    if (i0 >= n - 1) return 0.0f;
    int i1 = i0 + 1;

    const float2 zi0 = __ldg(&z0[i0]);
    const float2 vi0 = __ldg(&v0[i0]);
    float acc = 0.0f;

    if (i1 >= n) {
        // degenerate single row (n odd, last group)
        for (int j = i0 + 1 + (int)threadIdx.x; j < n; j += TPB)
            acc += pair_term<T0ZERO>(zi0, vi0, __ldg(&z0[j]), __ldg(&v0[j]),
                                     b, t0, tn);
        return acc;
    }

    const float2 zi1 = __ldg(&z0[i1]);
    const float2 vi1 = __ldg(&v0[i1]);

    // peel the (i0, i1) pair: exactly one thread does it
    if (threadIdx.x == 0)
        acc += pair_term<T0ZERO>(zi0, vi0, zi1, vi1, b, t0, tn);

    // branch-free: both rows valid for all j >= i0+2
    for (int j = i0 + 2 + (int)threadIdx.x; j < n; j += TPB) {
        float2 zj = __ldg(&z0[j]);
        float2 vj = __ldg(&v0[j]);
        acc += pair_term<T0ZERO>(zi0, vi0, zj, vj, b, t0, tn);
        acc += pair_term<T0ZERO>(zi1, vi1, zj, vj, b, t0, tn);
    }
    return acc;
}

// Snake-order pair sweep: pass p assigns block b the group
// p*P + (p even ? b : P-1-b). Consecutive pass pairs have constant cost sum
// (group cost is linear in g), so per-block totals are near-uniform.
template <bool T0ZERO>
__device__ __forceinline__ float snake_pairs(const float2* __restrict__ z0,
                                             const float2* __restrict__ v0,
                                             int n, int ngroups,
                                             float b, float t0, float tn) {
    const int P = gridDim.x;
    float acc = 0.0f;
    for (int p = 0; ; p++) {
        int base = p * P;
        if (base >= ngroups) break;
        int bb = (p & 1) ? (P - 1 - (int)blockIdx.x) : (int)blockIdx.x;
        int g  = base + bb;
        if (g < ngroups)
            acc += group_pairs<T0ZERO>(z0, v0, g, n, b, t0, tn);
    }
    return acc;
}

__global__ void __launch_bounds__(TPB, 7)
cvm_fused(const int2*   __restrict__ idx,
          const float*  __restrict__ t,
          const float2* __restrict__ z0,
          const float2* __restrict__ v0,
          const float*  __restrict__ t0p,
          const float*  __restrict__ tnp,
          const float*  __restrict__ betap,
          float*        __restrict__ out,
          int n, int n_events, int ngroups) {
    const float b  = __ldg(betap);
    const float t0 = __ldg(t0p);
    const float tn = __ldg(tnp);
    float acc = 0.0f;

    // ---- pair term (all blocks, snake-balanced) ----
    if (t0 == 0.0f)
        acc += snake_pairs<true >(z0, v0, n, ngroups, b, t0, tn);
    else
        acc += snake_pairs<false>(z0, v0, n, ngroups, b, t0, tn);

    // ---- event term (all blocks, uniform grid-stride) ----
    {
        int stride = (int)gridDim.x * TPB;
        for (int e = (int)blockIdx.x * TPB + (int)threadIdx.x; e < n_events;
             e += stride) {
            int2  ij = __ldg(&idx[e]);
            float te = __ldg(&t[e]);
            float2 zi = __ldg(&z0[ij.x]);
            float2 zj = __ldg(&z0[ij.y]);
            float2 vi = __ldg(&v0[ij.x]);
            float2 vj = __ldg(&v0[ij.y]);
            float dx = fmaf(vi.x - vj.x, te, zi.x - zj.x);
            float dy = fmaf(vi.y - vj.y, te, zi.y - zj.y);
            acc = fmaf(dx, dx, acc);
            acc = fmaf(dy, dy, acc);
        }
    }

    float bs = block_reduce_sum(acc);
    __shared__ unsigned int s_rank;
    if (threadIdx.x == 0) {
        g_part[blockIdx.x] = bs;
        __threadfence();
        s_rank = atomicAdd(&g_ctr, 1u);
    }
    __syncthreads();

    // ---- last finished block: final reduction + output ----
    if (s_rank == gridDim.x - 1) {
        __threadfence();
        double d = 0.0;
        for (int i = threadIdx.x; i < (int)gridDim.x; i += TPB)
            d += (double)g_part[i];
        __shared__ double sd[32];
        int lane = threadIdx.x & 31, w = threadIdx.x >> 5;
        #pragma unroll
        for (int o = 16; o; o >>= 1) d += __shfl_xor_sync(0xffffffffu, d, o);
        if (lane == 0) sd[w] = d;
        __syncthreads();
        d = (threadIdx.x < (TPB >> 5)) ? sd[threadIdx.x] : 0.0;
        if (w == 0) {
            #pragma unroll
            for (int o = 16; o; o >>= 1) d += __shfl_xor_sync(0xffffffffu, d, o);
        }
        if (threadIdx.x == 0) {
            out[0] = (float)((double)n_events * (double)b - d);
            g_ctr = 0;             // self-reset for next graph replay
            __threadfence();
        }
    }
}

extern "C" void kernel_launch(void* const* d_in, const int* in_sizes, int n_in,
                              void* d_out, int out_size) {
    const int2*   idx  = (const int2*)d_in[0];    // (N_EVENTS, 2) int32
    const float*  t    = (const float*)d_in[1];   // (N_EVENTS,)
    const float*  t0   = (const float*)d_in[2];   // scalar
    const float*  tn   = (const float*)d_in[3];   // scalar
    const float2* z0   = (const float2*)d_in[4];  // (N_POINTS, 2)
    const float2* v0   = (const float2*)d_in[5];  // (N_POINTS, 2)
    const float*  beta = (const float*)d_in[6];   // (1,1)

    const int n_events = in_sizes[1];
    const int n_points = in_sizes[4] / 2;

    const int ngroups = (n_points + 1) / 2;   // dual-row groups

    // 7 blocks/SM x 148 SMs: exactly one wave, uniform per-SM residency.
    int grid = 7 * 148;
    if (grid > MAXB) grid = MAXB;

    cvm_fused<<<grid, TPB>>>(idx, t, z0, v0, t0, tn, beta,
                             (float*)d_out, n_points, n_events, ngroups);
}

// round 6
// speedup vs baseline: 1.1088x; 1.0403x over previous
#include <cuda_runtime.h>

#define TPB  256
#define MAXB 8192

typedef unsigned long long u64;

__device__ float        g_part[MAXB];
__device__ unsigned int g_ctr = 0;

__device__ __forceinline__ float rcp_approx(float x) {
    float r; asm("rcp.approx.f32 %0, %1;" : "=f"(r) : "f"(x)); return r;
}
__device__ __forceinline__ float ex2_approx(float x) {
    float r; asm("ex2.approx.f32 %0, %1;" : "=f"(r) : "f"(x)); return r;
}
#define L2E 1.4426950408889634f

// ---------- packed f32x2 helpers ----------
__device__ __forceinline__ u64 f2pk(float lo, float hi) {
    u64 r; asm("mov.b64 %0, {%1, %2};" : "=l"(r) : "f"(lo), "f"(hi)); return r;
}
__device__ __forceinline__ void f2up(u64 v, float& lo, float& hi) {
    asm("mov.b64 {%0, %1}, %2;" : "=f"(lo), "=f"(hi) : "l"(v));
}
__device__ __forceinline__ u64 f2add(u64 a, u64 b) {
    u64 d; asm("add.rn.f32x2 %0, %1, %2;" : "=l"(d) : "l"(a), "l"(b)); return d;
}
__device__ __forceinline__ u64 f2mul(u64 a, u64 b) {
    u64 d; asm("mul.rn.f32x2 %0, %1, %2;" : "=l"(d) : "l"(a), "l"(b)); return d;
}
__device__ __forceinline__ u64 f2fma(u64 a, u64 b, u64 c) {
    u64 d; asm("fma.rn.f32x2 %0, %1, %2, %3;" : "=l"(d) : "l"(a), "l"(b), "l"(c)); return d;
}
__device__ __forceinline__ u64 f2rsqrt(u64 v) {
    float lo, hi; f2up(v, lo, hi); return f2pk(rsqrtf(lo), rsqrtf(hi));
}
__device__ __forceinline__ u64 f2ex2(u64 v) {
    float lo, hi; f2up(v, lo, hi); return f2pk(ex2_approx(lo), ex2_approx(hi));
}
__device__ __forceinline__ u64 f2rcp(u64 v) {
    float lo, hi; f2up(v, lo, hi); return f2pk(rcp_approx(lo), rcp_approx(hi));
}

// ---------- scalar erf pieces (fallback paths) ----------
__device__ __forceinline__ float erf_as(float x) {
    float s  = copysignf(1.0f, x);
    float ax = fabsf(x);
    float t  = rcp_approx(fmaf(0.47047f, ax, 1.0f));
    float P  = t * fmaf(t, fmaf(t, 0.7478556f, -0.0958798f), 0.3480242f);
    float e  = ex2_approx(-ax * ax * L2E);
    return s * fmaf(-P, e, 1.0f);
}
__device__ __forceinline__ float erf_small(float x, float u) {
    float p = fmaf(u, fmaf(u, fmaf(u, -2.3809524e-2f, 0.1f), -0.33333334f), 1.0f);
    return 1.1283791671f * x * p;
}

__device__ __forceinline__ float block_reduce_sum(float v) {
    __shared__ float s[32];
    int lane = threadIdx.x & 31;
    int w    = threadIdx.x >> 5;
    #pragma unroll
    for (int o = 16; o; o >>= 1) v += __shfl_xor_sync(0xffffffffu, v, o);
    if (lane == 0) s[w] = v;
    __syncthreads();
    v = (threadIdx.x < (TPB >> 5)) ? s[threadIdx.x] : 0.0f;
    if (w == 0) {
        #pragma unroll
        for (int o = 16; o; o >>= 1) v += __shfl_xor_sync(0xffffffffu, v, o);
    }
    return v;  // valid in thread 0
}

// scalar pair term (peel / odd-row / general t0 fallback)
template <bool T0ZERO>
__device__ __forceinline__ float pair_term(float2 zi, float2 vi,
                                           float2 zj, float2 vj,
                                           float b, float t0, float tn) {
    float dzx = zi.x - zj.x, dzy = zi.y - zj.y;
    float dvx = vi.x - vj.x, dvy = vi.y - vj.y;
    float a2 = fmaf(dzx, dzx, dzy * dzy);
    float b2 = fmaf(dvx, dvx, dvy * dvy);
    float ab = fmaf(dzx, dvx, dzy * dvy);
    float rb = rsqrtf(b2);
    float bn = b2 * rb;
    float q  = ab * rb;
    float u  = q * q;
    float earg  = (b - a2) + u;
    float pref0 = 0.88622692545275801f * rb;
    float pref  = ex2_approx(earg * L2E) * pref0;
    if (T0ZERO) {
        float e0 = erf_small(q, u);
        float x1 = fmaf(bn, tn, q);
        float s  = copysignf(1.0f, x1);
        float ax = fabsf(x1);
        float t  = rcp_approx(fmaf(0.47047f, ax, 1.0f));
        float P  = t * fmaf(t, fmaf(t, 0.7478556f, -0.0958798f), 0.3480242f);
        float S  = ex2_approx(fmaf(-x1, x1, earg) * L2E);
        return fmaf(pref, s - e0, -pref0 * S * (s * P));
    } else {
        float e1 = erf_as(fmaf(bn, tn, q));
        float e0 = erf_as(fmaf(bn, t0, q));
        return pref * (e1 - e0);
    }
}

// ---------- packed dual-row group (t0 == 0 fast path) ----------
__device__ __forceinline__ float group_pairs_p2(const float2* __restrict__ z0,
                                                const float2* __restrict__ v0,
                                                int g, int n,
                                                float b, float tn) {
    const int i0 = 2 * g;
    if (i0 >= n - 1) return 0.0f;
    const int i1 = i0 + 1;

    const float2 zi0 = __ldg(&z0[i0]);
    const float2 vi0 = __ldg(&v0[i0]);
    float acc_s = 0.0f;

    if (i1 >= n) {  // odd-n tail: single row, scalar
        for (int j = i0 + 1 + (int)threadIdx.x; j < n; j += TPB)
            acc_s += pair_term<true>(zi0, vi0, __ldg(&z0[j]), __ldg(&v0[j]),
                                     b, 0.0f, tn);
        return acc_s;
    }

    const float2 zi1 = __ldg(&z0[i1]);
    const float2 vi1 = __ldg(&v0[i1]);
    if (threadIdx.x == 0)
        acc_s = pair_term<true>(zi0, vi0, zi1, vi1, b, 0.0f, tn);

    const u64 zix = f2pk(zi0.x, zi1.x), ziy = f2pk(zi0.y, zi1.y);
    const u64 vix = f2pk(vi0.x, vi1.x), viy = f2pk(vi0.y, vi1.y);

    const u64 NEG1 = f2pk(-1.0f, -1.0f);
    const u64 ONE2 = f2pk(1.0f, 1.0f);
    const u64 Bc   = f2pk(b, b);
    const u64 TN2  = f2pk(tn, tn);
    const u64 L2E2 = f2pk(L2E, L2E);
    const u64 SQP2 = f2pk(0.88622692545275801f, 0.88622692545275801f);
    const u64 CSP  = f2pk(1.1283791671f, 1.1283791671f);
    const u64 C1   = f2pk(-0.33333334f, -0.33333334f);
    const u64 C2   = f2pk(0.1f, 0.1f);
    const u64 C3   = f2pk(-2.3809524e-2f, -2.3809524e-2f);
    const u64 PP   = f2pk(0.47047f, 0.47047f);
    const u64 A1   = f2pk(0.3480242f, 0.3480242f);
    const u64 A2   = f2pk(-0.0958798f, -0.0958798f);
    const u64 A3   = f2pk(0.7478556f, 0.7478556f);
    const u64 SMSK = 0x8000000080000000ull;

    u64 acc2 = 0;  // (0.0f, 0.0f)

    for (int j = i0 + 2 + (int)threadIdx.x; j < n; j += TPB) {
        float2 zj = __ldg(&z0[j]);
        float2 vj = __ldg(&v0[j]);
        u64 zjx = f2pk(zj.x, zj.x), zjy = f2pk(zj.y, zj.y);
        u64 vjx = f2pk(vj.x, vj.x), vjy = f2pk(vj.y, vj.y);

        u64 dzx = f2fma(zjx, NEG1, zix);     // zi - zj
        u64 dzy = f2fma(zjy, NEG1, ziy);
        u64 dvx = f2fma(vjx, NEG1, vix);
        u64 dvy = f2fma(vjy, NEG1, viy);

        u64 a2 = f2fma(dzx, dzx, f2mul(dzy, dzy));
        u64 b2 = f2fma(dvx, dvx, f2mul(dvy, dvy));
        u64 ab = f2fma(dzx, dvx, f2mul(dzy, dvy));

        u64 rb = f2rsqrt(b2);
        u64 bn = f2mul(b2, rb);
        u64 q  = f2mul(ab, rb);
        u64 u  = f2mul(q, q);
        u64 earg = f2add(f2fma(a2, NEG1, Bc), u);   // (b - a2) + u
        u64 p0   = f2mul(rb, SQP2);
        u64 pref = f2mul(f2ex2(f2mul(earg, L2E2)), p0);

        // e0 = erf(q), |q| <= 0.708 Taylor
        u64 p  = f2fma(u, f2fma(u, f2fma(u, C3, C2), C1), ONE2);
        u64 e0 = f2mul(f2mul(q, CSP), p);

        u64 x1  = f2fma(bn, TN2, q);
        u64 sgn = x1 & SMSK;
        u64 ax  = x1 & ~SMSK;
        u64 t   = f2rcp(f2fma(ax, PP, ONE2));
        u64 P   = f2mul(t, f2fma(t, f2fma(t, A3, A2), A1));

        u64 nx1 = x1 ^ SMSK;
        u64 S   = f2ex2(f2mul(f2fma(nx1, x1, earg), L2E2));

        u64 s1  = 0x3F8000003F800000ull | sgn;      // +-1.0f
        u64 se0 = f2fma(e0, NEG1, s1);              // s - e0
        u64 nsP = P ^ (nx1 & SMSK);                 // -s*P  (P > 0)

        acc2 = f2fma(pref, se0, acc2);
        acc2 = f2fma(f2mul(p0, S), nsP, acc2);
    }

    float lo, hi; f2up(acc2, lo, hi);
    return acc_s + lo + hi;
}

// scalar general-t0 group (rare path)
__device__ __forceinline__ float group_pairs_gen(const float2* __restrict__ z0,
                                                 const float2* __restrict__ v0,
                                                 int g, int n,
                                                 float b, float t0, float tn) {
    int i0 = 2 * g;
    if (i0 >= n - 1) return 0.0f;
    int i1 = i0 + 1;
    const float2 zi0 = __ldg(&z0[i0]);
    const float2 vi0 = __ldg(&v0[i0]);
    float acc = 0.0f;
    for (int j = i0 + 1 + (int)threadIdx.x; j < n; j += TPB)
        acc += pair_term<false>(zi0, vi0, __ldg(&z0[j]), __ldg(&v0[j]), b, t0, tn);
    if (i1 < n) {
        const float2 zi1 = __ldg(&z0[i1]);
        const float2 vi1 = __ldg(&v0[i1]);
        for (int j = i1 + 1 + (int)threadIdx.x; j < n; j += TPB)
            acc += pair_term<false>(zi1, vi1, __ldg(&z0[j]), __ldg(&v0[j]), b, t0, tn);
    }
    return acc;
}

__global__ void __launch_bounds__(TPB, 4)
cvm_fused(const int2*   __restrict__ idx,
          const float*  __restrict__ t,
          const float2* __restrict__ z0,
          const float2* __restrict__ v0,
          const float*  __restrict__ t0p,
          const float*  __restrict__ tnp,
          const float*  __restrict__ betap,
          float*        __restrict__ out,
          int n, int n_events, int ngroups) {
    const float b  = __ldg(betap);
    const float t0 = __ldg(t0p);
    const float tn = __ldg(tnp);
    float acc = 0.0f;

    // ---- pair term: snake-balanced grid-stride over dual-row groups ----
    {
        const int P = gridDim.x;
        const bool t0z = (t0 == 0.0f);
        for (int p = 0; ; p++) {
            int base = p * P;
            if (base >= ngroups) break;
            int bb = (p & 1) ? (P - 1 - (int)blockIdx.x) : (int)blockIdx.x;
            int g  = base + bb;
            if (g < ngroups) {
                if (t0z) acc += group_pairs_p2 (z0, v0, g, n, b, tn);
                else     acc += group_pairs_gen(z0, v0, g, n, b, t0, tn);
            }
        }
    }

    // ---- event term (all blocks, uniform grid-stride) ----
    {
        int stride = (int)gridDim.x * TPB;
        for (int e = (int)blockIdx.x * TPB + (int)threadIdx.x; e < n_events;
             e += stride) {
            int2  ij = __ldg(&idx[e]);
            float te = __ldg(&t[e]);
            float2 zi = __ldg(&z0[ij.x]);
            float2 zj = __ldg(&z0[ij.y]);
            float2 vi = __ldg(&v0[ij.x]);
            float2 vj = __ldg(&v0[ij.y]);
            float dx = fmaf(vi.x - vj.x, te, zi.x - zj.x);
            float dy = fmaf(vi.y - vj.y, te, zi.y - zj.y);
            acc = fmaf(dx, dx, acc);
            acc = fmaf(dy, dy, acc);
        }
    }

    float bs = block_reduce_sum(acc);
    __shared__ unsigned int s_rank;
    if (threadIdx.x == 0) {
        g_part[blockIdx.x] = bs;
        __threadfence();
        s_rank = atomicAdd(&g_ctr, 1u);
    }
    __syncthreads();

    if (s_rank == gridDim.x - 1) {
        __threadfence();
        double d = 0.0;
        for (int i = threadIdx.x; i < (int)gridDim.x; i += TPB)
            d += (double)g_part[i];
        __shared__ double sd[32];
        int lane = threadIdx.x & 31, w = threadIdx.x >> 5;
        #pragma unroll
        for (int o = 16; o; o >>= 1) d += __shfl_xor_sync(0xffffffffu, d, o);
        if (lane == 0) sd[w] = d;
        __syncthreads();
        d = (threadIdx.x < (TPB >> 5)) ? sd[threadIdx.x] : 0.0;
        if (w == 0) {
            #pragma unroll
            for (int o = 16; o; o >>= 1) d += __shfl_xor_sync(0xffffffffu, d, o);
        }
        if (threadIdx.x == 0) {
            out[0] = (float)((double)n_events * (double)b - d);
            g_ctr = 0;             // self-reset for next graph replay
            __threadfence();
        }
    }
}

extern "C" void kernel_launch(void* const* d_in, const int* in_sizes, int n_in,
                              void* d_out, int out_size) {
    const int2*   idx  = (const int2*)d_in[0];    // (N_EVENTS, 2) int32
    const float*  t    = (const float*)d_in[1];   // (N_EVENTS,)
    const float*  t0   = (const float*)d_in[2];   // scalar
    const float*  tn   = (const float*)d_in[3];   // scalar
    const float2* z0   = (const float2*)d_in[4];  // (N_POINTS, 2)
    const float2* v0   = (const float2*)d_in[5];  // (N_POINTS, 2)
    const float*  beta = (const float*)d_in[6];   // (1,1)

    const int n_events = in_sizes[1];
    const int n_points = in_sizes[4] / 2;

    const int ngroups = (n_points + 1) / 2;   // dual-row groups

    // 4 blocks/SM x 148 SMs, <=64 regs: exactly one wave.
    int grid = 4 * 148;
    if (grid > MAXB) grid = MAXB;

    cvm_fused<<<grid, TPB>>>(idx, t, z0, v0, t0, tn, beta,
                             (float*)d_out, n_points, n_events, ngroups);
}

// round 7
// speedup vs baseline: 1.3299x; 1.1994x over previous
#include <cuda_runtime.h>

#define TPB  256
#define MAXB 8192

typedef unsigned long long u64;

__device__ float        g_part[MAXB];
__device__ unsigned int g_ctr = 0;

__device__ __forceinline__ float ex2_approx(float x) {
    float r; asm("ex2.approx.f32 %0, %1;" : "=f"(r) : "f"(x)); return r;
}
__device__ __forceinline__ float tanh_approx(float x) {
    float r; asm("tanh.approx.f32 %0, %1;" : "=f"(r) : "f"(x)); return r;
}
#define L2E 1.4426950408889634f
#define EK1 1.1283792f      // erf-tanh linear coeff
#define EK3 0.100906f       // erf-tanh cubic coeff

// ---------- packed f32x2 helpers ----------
__device__ __forceinline__ u64 f2pk(float lo, float hi) {
    u64 r; asm("mov.b64 %0, {%1, %2};" : "=l"(r) : "f"(lo), "f"(hi)); return r;
}
__device__ __forceinline__ void f2up(u64 v, float& lo, float& hi) {
    asm("mov.b64 {%0, %1}, %2;" : "=f"(lo), "=f"(hi) : "l"(v));
}
__device__ __forceinline__ u64 f2add(u64 a, u64 b) {
    u64 d; asm("add.rn.f32x2 %0, %1, %2;" : "=l"(d) : "l"(a), "l"(b)); return d;
}
__device__ __forceinline__ u64 f2mul(u64 a, u64 b) {
    u64 d; asm("mul.rn.f32x2 %0, %1, %2;" : "=l"(d) : "l"(a), "l"(b)); return d;
}
__device__ __forceinline__ u64 f2fma(u64 a, u64 b, u64 c) {
    u64 d; asm("fma.rn.f32x2 %0, %1, %2, %3;" : "=l"(d) : "l"(a), "l"(b), "l"(c)); return d;
}
__device__ __forceinline__ u64 f2rsqrt(u64 v) {
    float lo, hi; f2up(v, lo, hi); return f2pk(rsqrtf(lo), rsqrtf(hi));
}
__device__ __forceinline__ u64 f2ex2(u64 v) {
    float lo, hi; f2up(v, lo, hi); return f2pk(ex2_approx(lo), ex2_approx(hi));
}
__device__ __forceinline__ u64 f2tanh(u64 v) {
    float lo, hi; f2up(v, lo, hi); return f2pk(tanh_approx(lo), tanh_approx(hi));
}

// ---------- scalar erf pieces ----------
// erf via tanh identity (abs err < ~3.5e-4, saturates correctly, odd)
__device__ __forceinline__ float erf_tanh(float x) {
    return tanh_approx(x * fmaf(EK3, x * x, EK1));
}
// Taylor erf for |x| <= 0.71 (abs err < 3e-4, 0 MUFU); takes u = x*x
__device__ __forceinline__ float erf_small(float x, float u) {
    float p = fmaf(u, fmaf(u, fmaf(u, -2.3809524e-2f, 0.1f), -0.33333334f), 1.0f);
    return 1.1283791671f * x * p;
}

__device__ __forceinline__ float block_reduce_sum(float v) {
    __shared__ float s[32];
    int lane = threadIdx.x & 31;
    int w    = threadIdx.x >> 5;
    #pragma unroll
    for (int o = 16; o; o >>= 1) v += __shfl_xor_sync(0xffffffffu, v, o);
    if (lane == 0) s[w] = v;
    __syncthreads();
    v = (threadIdx.x < (TPB >> 5)) ? s[threadIdx.x] : 0.0f;
    if (w == 0) {
        #pragma unroll
        for (int o = 16; o; o >>= 1) v += __shfl_xor_sync(0xffffffffu, v, o);
    }
    return v;  // valid in thread 0
}

// scalar pair term (peel / odd-row / general-t0 fallback)
template <bool T0ZERO>
__device__ __forceinline__ float pair_term(float2 zi, float2 vi,
                                           float2 zj, float2 vj,
                                           float b, float t0, float tn) {
    float dzx = zi.x - zj.x, dzy = zi.y - zj.y;
    float dvx = vi.x - vj.x, dvy = vi.y - vj.y;
    float a2 = fmaf(dzx, dzx, dzy * dzy);
    float b2 = fmaf(dvx, dvx, dvy * dvy);
    float ab = fmaf(dzx, dvx, dzy * dvy);
    float rb = rsqrtf(b2);
    float bn = b2 * rb;
    float q  = ab * rb;
    float u  = q * q;
    float earg  = (b - a2) + u;
    float pref  = ex2_approx(earg * L2E) * (0.88622692545275801f * rb);
    float e1 = erf_tanh(fmaf(bn, tn, q));
    float e0 = T0ZERO ? erf_small(q, u) : erf_tanh(fmaf(bn, t0, q));
    return pref * (e1 - e0);
}

// ---------- packed dual-row group (t0 == 0 fast path) ----------
__device__ __forceinline__ float group_pairs_p2(const float2* __restrict__ z0,
                                                const float2* __restrict__ v0,
                                                int g, int n,
                                                float b, float tn) {
    const int i0 = 2 * g;
    if (i0 >= n - 1) return 0.0f;
    const int i1 = i0 + 1;

    const float2 zi0 = __ldg(&z0[i0]);
    const float2 vi0 = __ldg(&v0[i0]);
    float acc_s = 0.0f;

    if (i1 >= n) {  // odd-n tail: single row, scalar
        for (int j = i0 + 1 + (int)threadIdx.x; j < n; j += TPB)
            acc_s += pair_term<true>(zi0, vi0, __ldg(&z0[j]), __ldg(&v0[j]),
                                     b, 0.0f, tn);
        return acc_s;
    }

    const float2 zi1 = __ldg(&z0[i1]);
    const float2 vi1 = __ldg(&v0[i1]);
    if (threadIdx.x == 0)
        acc_s = pair_term<true>(zi0, vi0, zi1, vi1, b, 0.0f, tn);

    const u64 zix = f2pk(zi0.x, zi1.x), ziy = f2pk(zi0.y, zi1.y);
    const u64 vix = f2pk(vi0.x, vi1.x), viy = f2pk(vi0.y, vi1.y);

    const u64 NEG1 = f2pk(-1.0f, -1.0f);
    const u64 ONE2 = f2pk(1.0f, 1.0f);
    const u64 Bc   = f2pk(b, b);
    const u64 TN2  = f2pk(tn, tn);
    const u64 L2E2 = f2pk(L2E, L2E);
    const u64 SQP2 = f2pk(0.88622692545275801f, 0.88622692545275801f);
    const u64 CSP  = f2pk(1.1283791671f, 1.1283791671f);
    const u64 C1   = f2pk(-0.33333334f, -0.33333334f);
    const u64 C2   = f2pk(0.1f, 0.1f);
    const u64 C3   = f2pk(-2.3809524e-2f, -2.3809524e-2f);
    const u64 K1   = f2pk(EK1, EK1);
    const u64 K3   = f2pk(EK3, EK3);

    u64 acc2 = 0;  // (0.0f, 0.0f)

    #pragma unroll 2
    for (int j = i0 + 2 + (int)threadIdx.x; j < n; j += TPB) {
        float2 zj = __ldg(&z0[j]);
        float2 vj = __ldg(&v0[j]);
        u64 zjx = f2pk(zj.x, zj.x), zjy = f2pk(zj.y, zj.y);
        u64 vjx = f2pk(vj.x, vj.x), vjy = f2pk(vj.y, vj.y);

        u64 dzx = f2fma(zjx, NEG1, zix);     // zi - zj
        u64 dzy = f2fma(zjy, NEG1, ziy);
        u64 dvx = f2fma(vjx, NEG1, vix);
        u64 dvy = f2fma(vjy, NEG1, viy);

        u64 a2 = f2fma(dzx, dzx, f2mul(dzy, dzy));
        u64 b2 = f2fma(dvx, dvx, f2mul(dvy, dvy));
        u64 ab = f2fma(dzx, dvx, f2mul(dzy, dvy));

        u64 rb = f2rsqrt(b2);
        u64 bn = f2mul(b2, rb);
        u64 q  = f2mul(ab, rb);
        u64 u  = f2mul(q, q);
        u64 earg = f2add(f2fma(a2, NEG1, Bc), u);   // (b - a2) + u
        u64 pref = f2mul(f2ex2(f2mul(earg, L2E2)), f2mul(rb, SQP2));

        // e0 = erf(q), |q| <= 0.708 Taylor (odd, sign-free)
        u64 p  = f2fma(u, f2fma(u, f2fma(u, C3, C2), C1), ONE2);
        u64 e0 = f2mul(f2mul(q, CSP), p);

        // e1 = erf(x1) via tanh identity (odd, saturating, sign-free)
        u64 x1 = f2fma(bn, TN2, q);
        u64 w  = f2mul(x1, x1);
        u64 e1 = f2tanh(f2mul(x1, f2fma(K3, w, K1)));

        acc2 = f2fma(pref, f2fma(e0, NEG1, e1), acc2);
    }

    float lo, hi; f2up(acc2, lo, hi);
    return acc_s + lo + hi;
}

// scalar general-t0 group (rare path)
__device__ __forceinline__ float group_pairs_gen(const float2* __restrict__ z0,
                                                 const float2* __restrict__ v0,
                                                 int g, int n,
                                                 float b, float t0, float tn) {
    int i0 = 2 * g;
    if (i0 >= n - 1) return 0.0f;
    int i1 = i0 + 1;
    const float2 zi0 = __ldg(&z0[i0]);
    const float2 vi0 = __ldg(&v0[i0]);
    float acc = 0.0f;
    for (int j = i0 + 1 + (int)threadIdx.x; j < n; j += TPB)
        acc += pair_term<false>(zi0, vi0, __ldg(&z0[j]), __ldg(&v0[j]), b, t0, tn);
    if (i1 < n) {
        const float2 zi1 = __ldg(&z0[i1]);
        const float2 vi1 = __ldg(&v0[i1]);
        for (int j = i1 + 1 + (int)threadIdx.x; j < n; j += TPB)
            acc += pair_term<false>(zi1, vi1, __ldg(&z0[j]), __ldg(&v0[j]), b, t0, tn);
    }
    return acc;
}

__global__ void __launch_bounds__(TPB, 4)
cvm_fused(const int2*   __restrict__ idx,
          const float*  __restrict__ t,
          const float2* __restrict__ z0,
          const float2* __restrict__ v0,
          const float*  __restrict__ t0p,
          const float*  __restrict__ tnp,
          const float*  __restrict__ betap,
          float*        __restrict__ out,
          int n, int n_events, int ngroups) {
    const float b  = __ldg(betap);
    const float t0 = __ldg(t0p);
    const float tn = __ldg(tnp);
    float acc = 0.0f;

    // ---- pair term: snake-balanced grid-stride over dual-row groups ----
    {
        const int P = gridDim.x;
        const bool t0z = (t0 == 0.0f);
        for (int p = 0; ; p++) {
            int base = p * P;
            if (base >= ngroups) break;
            int bb = (p & 1) ? (P - 1 - (int)blockIdx.x) : (int)blockIdx.x;
            int g  = base + bb;
            if (g < ngroups) {
                if (t0z) acc += group_pairs_p2 (z0, v0, g, n, b, tn);
                else     acc += group_pairs_gen(z0, v0, g, n, b, t0, tn);
            }
        }
    }

    // ---- event term (all blocks, uniform grid-stride) ----
    {
        int stride = (int)gridDim.x * TPB;
        for (int e = (int)blockIdx.x * TPB + (int)threadIdx.x; e < n_events;
             e += stride) {
            int2  ij = __ldg(&idx[e]);
            float te = __ldg(&t[e]);
            float2 zi = __ldg(&z0[ij.x]);
            float2 zj = __ldg(&z0[ij.y]);
            float2 vi = __ldg(&v0[ij.x]);
            float2 vj = __ldg(&v0[ij.y]);
            float dx = fmaf(vi.x - vj.x, te, zi.x - zj.x);
            float dy = fmaf(vi.y - vj.y, te, zi.y - zj.y);
            acc = fmaf(dx, dx, acc);
            acc = fmaf(dy, dy, acc);
        }
    }

    float bs = block_reduce_sum(acc);
    __shared__ unsigned int s_rank;
    if (threadIdx.x == 0) {
        g_part[blockIdx.x] = bs;
        __threadfence();
        s_rank = atomicAdd(&g_ctr, 1u);
    }
    __syncthreads();

    if (s_rank == gridDim.x - 1) {
        __threadfence();
        double d = 0.0;
        for (int i = threadIdx.x; i < (int)gridDim.x; i += TPB)
            d += (double)g_part[i];
        __shared__ double sd[32];
        int lane = threadIdx.x & 31, w = threadIdx.x >> 5;
        #pragma unroll
        for (int o = 16; o; o >>= 1) d += __shfl_xor_sync(0xffffffffu, d, o);
        if (lane == 0) sd[w] = d;
        __syncthreads();
        d = (threadIdx.x < (TPB >> 5)) ? sd[threadIdx.x] : 0.0;
        if (w == 0) {
            #pragma unroll
            for (int o = 16; o; o >>= 1) d += __shfl_xor_sync(0xffffffffu, d, o);
        }
        if (threadIdx.x == 0) {
            out[0] = (float)((double)n_events * (double)b - d);
            g_ctr = 0;             // self-reset for next graph replay
            __threadfence();
        }
    }
}

extern "C" void kernel_launch(void* const* d_in, const int* in_sizes, int n_in,
                              void* d_out, int out_size) {
    const int2*   idx  = (const int2*)d_in[0];    // (N_EVENTS, 2) int32
    const float*  t    = (const float*)d_in[1];   // (N_EVENTS,)
    const float*  t0   = (const float*)d_in[2];   // scalar
    const float*  tn   = (const float*)d_in[3];   // scalar
    const float2* z0   = (const float2*)d_in[4];  // (N_POINTS, 2)
    const float2* v0   = (const float2*)d_in[5];  // (N_POINTS, 2)
    const float*  beta = (const float*)d_in[6];   // (1,1)

    const int n_events = in_sizes[1];
    const int n_points = in_sizes[4] / 2;

    const int ngroups = (n_points + 1) / 2;   // dual-row groups

    // 4 blocks/SM x 148 SMs, <=64 regs: exactly one wave, snake-balanced.
    int grid = 4 * 148;
    if (grid > MAXB) grid = MAXB;

    cvm_fused<<<grid, TPB>>>(idx, t, z0, v0, t0, tn, beta,
                             (float*)d_out, n_points, n_events, ngroups);
}